// round 11
// baseline (speedup 1.0000x reference)
#include <cuda_runtime.h>
#include <mma.h>
#include <math.h>

using namespace nvcuda;

#define BLK 256           // threads per block = points per block
#define LD 68             // activation buffer row stride (floats, mult of 4)

typedef unsigned long long u64;

// ---- packed f32x2 helpers for the encoder lerps ----
__device__ __forceinline__ u64 pack2(float lo, float hi) {
    u64 r; asm("mov.b64 %0,{%1,%2};" : "=l"(r) : "f"(lo), "f"(hi)); return r;
}
__device__ __forceinline__ u64 fma2(u64 a, u64 b, u64 c) {
    u64 d; asm("fma.rn.f32x2 %0,%1,%2,%3;" : "=l"(d) : "l"(a), "l"(b), "l"(c));
    return d;
}
__device__ __forceinline__ u64 mul2(u64 a, u64 b) {
    u64 d; asm("mul.rn.f32x2 %0,%1,%2;" : "=l"(d) : "l"(a), "l"(b));
    return d;
}

template <class Frag>
__device__ __forceinline__ void to_tf32(Frag& f) {
    #pragma unroll
    for (int i = 0; i < f.num_elements; i++)
        f.x[i] = wmma::__float_to_tf32(f.x[i]);
}

// One MLP layer for this warp's 32 rows:  C = [relu](A @ B)
// A: [rows][8*KT] in shared, lda;  B: [8*KT][16*NT] row-major in shared, ldb;
// C: [rows][16*NT] in shared, ldc.
template <int KT, int NT, bool RELU>
__device__ __forceinline__ void mlp_layer(const float* A, int lda,
                                          const float* B, int ldb,
                                          float* C, int ldc, int r0)
{
    #pragma unroll
    for (int m = 0; m < 2; m++) {
        wmma::fragment<wmma::matrix_a, 16, 16, 8, wmma::precision::tf32,
                       wmma::row_major> a[KT];
        #pragma unroll
        for (int k = 0; k < KT; k++) {
            wmma::load_matrix_sync(a[k], A + (r0 + 16 * m) * lda + 8 * k, lda);
            to_tf32(a[k]);
        }
        #pragma unroll
        for (int n = 0; n < NT; n++) {
            wmma::fragment<wmma::accumulator, 16, 16, 8, float> c;
            wmma::fill_fragment(c, 0.0f);
            #pragma unroll
            for (int k = 0; k < KT; k++) {
                wmma::fragment<wmma::matrix_b, 16, 16, 8, wmma::precision::tf32,
                               wmma::row_major> b;
                wmma::load_matrix_sync(b, B + 8 * k * ldb + 16 * n, ldb);
                to_tf32(b);
                wmma::mma_sync(c, a[k], b, c);
            }
            if (RELU) {
                #pragma unroll
                for (int i = 0; i < c.num_elements; i++)
                    c.x[i] = fmaxf(c.x[i], 0.0f);
            }
            wmma::store_matrix_sync(C + (r0 + 16 * m) * ldc + 16 * n, c, ldc,
                                    wmma::mem_row_major);
        }
    }
}

__global__ void nerf_fused_kernel(const float* __restrict__ xyz,
                                  const float* __restrict__ dirp,
                                  const float* __restrict__ table,
                                  const float* __restrict__ ws1g,
                                  const float* __restrict__ ws2g,
                                  const float* __restrict__ wr1g,
                                  const float* __restrict__ wr2g,
                                  const float* __restrict__ wr3g,
                                  float* __restrict__ out, int N)
{
    extern __shared__ float smem[];
    float* bufA = smem;                    // [BLK][LD]
    float* bufB = bufA + BLK * LD;         // [BLK][LD]
    float* sw1  = bufB + BLK * LD;         // [32][64]
    float* sw2p = sw1 + 32 * 64;           // [64][32] (17 cols + zero pad)
    float* sr1  = sw2p + 64 * 32;          // [32][64]
    float* sr2  = sr1 + 32 * 64;           // [64][64]
    float* sr3p = sr2 + 64 * 64;           // [64][16] (3 cols + zero pad)

    const int t = threadIdx.x;

    // ---- stage weights (only cross-warp dependency in the kernel) ----
    for (int i = t; i < 2048; i += BLK) { sw1[i] = ws1g[i]; sr1[i] = wr1g[i]; }
    for (int i = t; i < 4096; i += BLK) sr2[i] = wr2g[i];
    for (int i = t; i < 2048; i += BLK) {
        int k = i >> 5, n = i & 31;
        sw2p[i] = (n < 17) ? ws2g[k * 17 + n] : 0.0f;
    }
    for (int i = t; i < 1024; i += BLK) {
        int k = i >> 4, n = i & 15;
        sr3p[i] = (n < 3) ? wr3g[k * 3 + n] : 0.0f;
    }
    __syncthreads();

    const int p = blockIdx.x * BLK + t;
    const bool valid = p < N;
    float* myrow = bufA + t * LD;

    // ------------------------------------------------------------------
    // Hash-grid encoding -> bufA[t][0..32)
    // ------------------------------------------------------------------
    if (valid) {
        float x = xyz[3 * p + 0];
        float y = xyz[3 * p + 1];
        float z = xyz[3 * p + 2];

        const int res_tab[16] = {16, 22, 30, 42, 58, 80, 111, 153,
                                 212, 294, 406, 561, 775, 1072, 1481, 2047};
        #pragma unroll
        for (int l = 0; l < 16; l++) {
            const int res = res_tab[l];
            float px = x * (float)res, py = y * (float)res, pz = z * (float)res;
            float fx = floorf(px), fy = floorf(py), fz = floorf(pz);
            float wx = px - fx, wy = py - fy, wz = pz - fz;
            unsigned ix = (unsigned)fx, iy = (unsigned)fy, iz = (unsigned)fz;

            unsigned i0, i1, i2, i3, i4, i5, i6, i7;
            if (res <= 79) {  // dense level
                unsigned s = (unsigned)(res + 1);
                unsigned ss = s * s;
                unsigned base = ix + iy * s + iz * ss;
                i0 = base;      i1 = base + 1;
                i2 = base + s;  i3 = base + s + 1;
                i4 = base + ss; i5 = i4 + 1;
                i6 = i4 + s;    i7 = i4 + s + 1;
            } else {          // hashed level
                const unsigned P1 = 2654435761u, P2 = 805459861u;
                const unsigned m = (1u << 19) - 1u;
                unsigned hx0 = ix, hx1 = ix + 1u;
                unsigned hy0 = iy * P1, hy1 = hy0 + P1;
                unsigned hz0 = iz * P2, hz1 = hz0 + P2;
                i0 = (hx0 ^ hy0 ^ hz0) & m; i1 = (hx1 ^ hy0 ^ hz0) & m;
                i2 = (hx0 ^ hy1 ^ hz0) & m; i3 = (hx1 ^ hy1 ^ hz0) & m;
                i4 = (hx0 ^ hy0 ^ hz1) & m; i5 = (hx1 ^ hy0 ^ hz1) & m;
                i6 = (hx0 ^ hy1 ^ hz1) & m; i7 = (hx1 ^ hy1 ^ hz1) & m;
            }

            const u64* tl = reinterpret_cast<const u64*>(table) + ((size_t)l << 19);
            u64 f0 = __ldg(tl + i0); u64 f1 = __ldg(tl + i1);
            u64 f2 = __ldg(tl + i2); u64 f3 = __ldg(tl + i3);
            u64 f4 = __ldg(tl + i4); u64 f5 = __ldg(tl + i5);
            u64 f6 = __ldg(tl + i6); u64 f7 = __ldg(tl + i7);

            float ox = 1.0f - wx, oy = 1.0f - wy, oz = 1.0f - wz;
            u64 wxp = pack2(wx, wx), oxp = pack2(ox, ox);
            u64 wyp = pack2(wy, wy), oyp = pack2(oy, oy);
            u64 wzp = pack2(wz, wz), ozp = pack2(oz, oz);

            u64 a0 = fma2(f1, wxp, mul2(f0, oxp));
            u64 a1 = fma2(f3, wxp, mul2(f2, oxp));
            u64 a2 = fma2(f5, wxp, mul2(f4, oxp));
            u64 a3 = fma2(f7, wxp, mul2(f6, oxp));
            u64 c0 = fma2(a1, wyp, mul2(a0, oyp));
            u64 c1 = fma2(a3, wyp, mul2(a2, oyp));
            u64 e  = fma2(c1, wzp, mul2(c0, ozp));
            *reinterpret_cast<u64*>(myrow + 2 * l) = e;
        }
    } else {
        #pragma unroll
        for (int k = 0; k < 32; k++) myrow[k] = 0.0f;
    }
    __syncwarp();

    const int w = t >> 5;
    const int r0 = w * 32;   // this warp owns rows [r0, r0+32) — all layers warp-local

    // Sigma layer 1: bufA[.,0:32] @ ws1 -> relu -> bufB[.,0:64]
    mlp_layer<4, 4, true>(bufA, LD, sw1, 64, bufB, LD, r0);
    __syncwarp();
    // Sigma layer 2: bufB[.,0:64] @ ws2p -> bufA[.,32:64]
    mlp_layer<8, 2, false>(bufB, LD, sw2p, 32, bufA + 32, LD, r0);
    __syncwarp();

    // ---- epilogue: sigma out, build rgb_in = [SH(dir) | geo_feat] ----
    if (valid) {
        out[3 * N + p] = fmaxf(myrow[32], 0.0f);   // sigma

        float dx = dirp[3 * p + 0] * 2.0f - 1.0f;
        float dy = dirp[3 * p + 1] * 2.0f - 1.0f;
        float dz = dirp[3 * p + 2] * 2.0f - 1.0f;
        float x2 = dx * dx, y2 = dy * dy, z2 = dz * dz;
        float xy = dx * dy, yz = dy * dz, xz = dx * dz;

        // geo_feat first (reads cols 33..48, writes 16..31 — disjoint)
        #pragma unroll
        for (int j = 0; j < 16; j++) myrow[16 + j] = myrow[33 + j];

        myrow[0]  = 0.28209479177387814f;
        myrow[1]  = -0.48860251190291987f * dy;
        myrow[2]  = 0.48860251190291987f * dz;
        myrow[3]  = -0.48860251190291987f * dx;
        myrow[4]  = 1.0925484305920792f * xy;
        myrow[5]  = -1.0925484305920792f * yz;
        myrow[6]  = 0.94617469575756f * z2 - 0.31539156525252f;
        myrow[7]  = -1.0925484305920792f * xz;
        myrow[8]  = 0.5462742152960396f * (x2 - y2);
        myrow[9]  = 0.5900435899266435f * dy * (-3.0f * x2 + y2);
        myrow[10] = 2.890611442640554f * xy * dz;
        myrow[11] = 0.4570457994644657f * dy * (1.0f - 5.0f * z2);
        myrow[12] = 0.3731763325901154f * dz * (5.0f * z2 - 3.0f);
        myrow[13] = 0.4570457994644657f * dx * (1.0f - 5.0f * z2);
        myrow[14] = 1.445305721320277f * dz * (x2 - y2);
        myrow[15] = 0.5900435899266435f * dx * (-x2 + 3.0f * y2);
    } else {
        #pragma unroll
        for (int k = 0; k < 32; k++) myrow[k] = 0.0f;
    }
    __syncwarp();

    // RGB layer 1: bufA[.,0:32] @ wr1 -> relu -> bufB[.,0:64]
    mlp_layer<4, 4, true>(bufA, LD, sr1, 64, bufB, LD, r0);
    __syncwarp();
    // RGB layer 2: bufB[.,0:64] @ wr2 -> relu -> bufA[.,0:64]
    mlp_layer<8, 4, true>(bufB, LD, sr2, 64, bufA, LD, r0);
    __syncwarp();
    // RGB layer 3: bufA[.,0:64] @ wr3p -> bufB[.,0:16]
    mlp_layer<8, 1, false>(bufA, LD, sr3p, 16, bufB, LD, r0);
    __syncwarp();

    if (valid) {
        float a0 = bufB[t * LD + 0];
        float a1 = bufB[t * LD + 1];
        float a2 = bufB[t * LD + 2];
        out[3 * p + 0] = 1.0f / (1.0f + __expf(-a0));
        out[3 * p + 1] = 1.0f / (1.0f + __expf(-a1));
        out[3 * p + 2] = 1.0f / (1.0f + __expf(-a2));
    }
}

extern "C" void kernel_launch(void* const* d_in, const int* in_sizes, int n_in,
                              void* d_out, int out_size)
{
    const float* xyz = (const float*)d_in[0];
    const float* dir = (const float*)d_in[1];
    const float* table = (const float*)d_in[2];
    float* out = (float*)d_out;

    int N = in_sizes[0] / 3;
    int blocks = (N + BLK - 1) / BLK;

    // dynamic smem: 2 activation buffers + all weights
    size_t smem_bytes = (size_t)(2 * BLK * LD + 32 * 64 + 64 * 32 +
                                 32 * 64 + 64 * 64 + 64 * 16) * sizeof(float);
    static bool attr_set = false;
    if (!attr_set) {
        cudaFuncSetAttribute(nerf_fused_kernel,
                             cudaFuncAttributeMaxDynamicSharedMemorySize,
                             (int)smem_bytes);
        attr_set = true;
    }

    nerf_fused_kernel<<<blocks, BLK, smem_bytes>>>(
        xyz, dir, table,
        (const float*)d_in[3], (const float*)d_in[4],
        (const float*)d_in[5], (const float*)d_in[6],
        (const float*)d_in[7], out, N);
}